// round 2
// baseline (speedup 1.0000x reference)
#include <cuda_runtime.h>
#include <cstdint>

#define NN 50000
#define NE 800000
typedef unsigned long long ull;

static __device__ __forceinline__ ull ffma2(ull a, ull b, ull c) {
    ull d; asm("fma.rn.f32x2 %0, %1, %2, %3;" : "=l"(d) : "l"(a), "l"(b), "l"(c)); return d;
}
static __device__ __forceinline__ ull pack2(float lo, float hi) {
    ull d; asm("mov.b64 %0, {%1, %2};" : "=l"(d) : "f"(lo), "f"(hi)); return d;
}
static __device__ __forceinline__ float2 unpack2(ull v) {
    float2 r; asm("mov.b64 {%0, %1}, %2;" : "=f"(r.x), "=f"(r.y) : "l"(v)); return r;
}
static __device__ __forceinline__ float silu_f(float x) { return __fdividef(x, 1.0f + __expf(-x)); }

#define INV_SQRT3 0.5773502691896258f
#define INV_SQRT2 0.7071067811865476f
#define INV_NEI   0.25f

__device__ int   g_count[NN];
__device__ int   g_off[NN + 1];
__device__ int   g_cursor[NN];
__device__ int   g_perm[NE];
__device__ float g_xs[NN * 32];
__device__ float g_xv[NN * 96];          // [n][c][32]
__device__ float g_w[(size_t)NE * 160];  // [e][160]
__device__ float g_as[NN * 64];
__device__ float g_av[NN * 288];         // [n][c][96]
__device__ float g_gate[NN * 32];

// ---------------- sort by dst ----------------
__global__ void k_zero() {
    int i = blockIdx.x * blockDim.x + threadIdx.x;
    if (i < NN) g_count[i] = 0;
}
__global__ void k_hist(const int* __restrict__ edst) {
    int e = blockIdx.x * blockDim.x + threadIdx.x;
    if (e < NE) atomicAdd(&g_count[edst[e]], 1);
}
__global__ void k_scan() {
    __shared__ int wsum[32];
    int tid = threadIdx.x, lane = tid & 31, wid = tid >> 5;
    int running = 0;
    for (int base = 0; base < NN; base += 1024) {
        int i = base + tid;
        int c = (i < NN) ? g_count[i] : 0;
        int x = c;
        #pragma unroll
        for (int d = 1; d < 32; d <<= 1) {
            int y = __shfl_up_sync(0xffffffffu, x, d);
            if (lane >= d) x += y;
        }
        if (lane == 31) wsum[wid] = x;
        __syncthreads();
        if (wid == 0) {
            int s = wsum[lane];
            #pragma unroll
            for (int d = 1; d < 32; d <<= 1) {
                int y = __shfl_up_sync(0xffffffffu, s, d);
                if (lane >= d) s += y;
            }
            wsum[lane] = s;
        }
        __syncthreads();
        int prev = (wid > 0) ? wsum[wid - 1] : 0;
        int excl = running + prev + x - c;
        if (i < NN) { g_off[i] = excl; g_cursor[i] = excl; }
        running += wsum[31];
        __syncthreads();
    }
    if (tid == 0) g_off[NN] = running;
}
__global__ void k_scatter(const int* __restrict__ edst) {
    int e = blockIdx.x * blockDim.x + threadIdx.x;
    if (e < NE) g_perm[atomicAdd(&g_cursor[edst[e]], 1)] = e;
}

// ---------------- stage A: x_s = s@W1s, x_v = einsum(v,W1v) ----------------
__global__ __launch_bounds__(256) void k_stageA(const float* __restrict__ nf,
                                                const float* __restrict__ W1s,
                                                const float* __restrict__ W1v) {
    int n = blockIdx.x * blockDim.x + threadIdx.x;
    if (n >= NN) return;
    float s[32];
    const float4* p = (const float4*)(nf + (size_t)n * 128);
    #pragma unroll
    for (int q = 0; q < 8; q++) {
        float4 f = p[q];
        s[4*q] = f.x; s[4*q+1] = f.y; s[4*q+2] = f.z; s[4*q+3] = f.w;
    }
    for (int og = 0; og < 8; og++) {
        float4 acc = make_float4(0.f,0.f,0.f,0.f);
        #pragma unroll
        for (int u = 0; u < 32; u++) {
            float4 w = __ldg((const float4*)(W1s + u*32) + og);
            acc.x += s[u]*w.x; acc.y += s[u]*w.y; acc.z += s[u]*w.z; acc.w += s[u]*w.w;
        }
        *(float4*)(g_xs + (size_t)n*32 + og*4) = acc;
    }
    for (int c = 0; c < 3; c++) {
        float vc[32];
        #pragma unroll
        for (int u = 0; u < 32; u++) vc[u] = nf[(size_t)n*128 + 32 + 3*u + c];
        for (int og = 0; og < 8; og++) {
            float4 acc = make_float4(0.f,0.f,0.f,0.f);
            #pragma unroll
            for (int u = 0; u < 32; u++) {
                float4 w = __ldg((const float4*)(W1v + u*32) + og);
                acc.x += vc[u]*w.x; acc.y += vc[u]*w.y; acc.z += vc[u]*w.z; acc.w += vc[u]*w.w;
            }
            *(float4*)(g_xv + (size_t)n*96 + c*32 + og*4) = acc;
        }
    }
}

// ---------------- edge MLP: w = silu(emb@fc1+b)@fc2 ----------------
__global__ __launch_bounds__(128) void k_mlp(const float* __restrict__ emb,
                                             const float* __restrict__ w1,
                                             const float* __restrict__ b1,
                                             const float* __restrict__ w2) {
    __shared__ float sh_h[64 * 128];
    int tid = threadIdx.x;
    int e = blockIdx.x * 128 + tid;
    bool valid = (e < NE);
    int ee = valid ? e : 0;
    float x[8];
    {
        const float4* ep = (const float4*)(emb + (size_t)ee * 8);
        float4 xa = ep[0], xb = ep[1];
        x[0]=xa.x; x[1]=xa.y; x[2]=xa.z; x[3]=xa.w;
        x[4]=xb.x; x[5]=xb.y; x[6]=xb.z; x[7]=xb.w;
    }
    for (int j4 = 0; j4 < 16; j4++) {
        float4 acc = __ldg((const float4*)b1 + j4);
        #pragma unroll
        for (int i = 0; i < 8; i++) {
            float4 w = __ldg((const float4*)(w1 + i*64) + j4);
            acc.x += x[i]*w.x; acc.y += x[i]*w.y; acc.z += x[i]*w.z; acc.w += x[i]*w.w;
        }
        sh_h[(4*j4+0)*128 + tid] = silu_f(acc.x);
        sh_h[(4*j4+1)*128 + tid] = silu_f(acc.y);
        sh_h[(4*j4+2)*128 + tid] = silu_f(acc.z);
        sh_h[(4*j4+3)*128 + tid] = silu_f(acc.w);
    }
    __syncthreads();
    if (!valid) return;
    for (int ob = 0; ob < 20; ob++) {
        ull a0=0ULL, a1=0ULL, a2=0ULL, a3=0ULL;
        for (int k = 0; k < 64; k++) {
            float hk = sh_h[k*128 + tid];
            ull h2 = pack2(hk, hk);
            const ulonglong2* wp = (const ulonglong2*)(w2 + k*160 + ob*8);
            ulonglong2 wA = __ldg(wp);
            ulonglong2 wB = __ldg(wp + 1);
            a0 = ffma2(h2, wA.x, a0);
            a1 = ffma2(h2, wA.y, a1);
            a2 = ffma2(h2, wB.x, a2);
            a3 = ffma2(h2, wB.y, a3);
        }
        float2 r0 = unpack2(a0), r1 = unpack2(a1), r2 = unpack2(a2), r3 = unpack2(a3);
        float4* op = (float4*)(g_w + (size_t)e*160 + ob*8);
        op[0] = make_float4(r0.x, r0.y, r1.x, r1.y);
        op[1] = make_float4(r2.x, r2.y, r3.x, r3.y);
    }
}

// ---------------- aggregation: warp per node ----------------
__global__ __launch_bounds__(256) void k_agg(const int* __restrict__ esrc,
                                             const float* __restrict__ eattr) {
    int n = (blockIdx.x * 256 + threadIdx.x) >> 5;
    int lane = threadIdx.x & 31;
    if (n >= NN) return;
    int start = g_off[n], end = g_off[n + 1];
    float as0=0, as1=0;
    float av00=0, av01=0, av02=0, av10=0, av11=0, av12=0, av20=0, av21=0, av22=0;
    for (int idx = start; idx < end; idx++) {
        int e = g_perm[idx];
        int src = esrc[e];
        float4 ea = *(const float4*)(eattr + (size_t)e * 4);
        float sh0 = ea.x, s1 = ea.y, s2 = ea.z, s3 = ea.w;
        float xs  = g_xs[(size_t)src*32 + lane];
        const float* xvp = g_xv + (size_t)src*96;
        float xv0 = xvp[lane], xv1 = xvp[32+lane], xv2 = xvp[64+lane];
        const float* we = g_w + (size_t)e*160;
        float w00 = we[lane], w01 = we[32+lane], w10 = we[64+lane];
        float w11s = we[96+lane], w11v = we[128+lane];

        as0 += w00 * xs * sh0;
        as1 += (w11s * INV_SQRT3) * (xv0*s1 + xv1*s2 + xv2*s3);
        float t = w01 * xs;
        av00 += t*s1; av01 += t*s2; av02 += t*s3;
        float g = w10 * sh0;
        av10 += g*xv0; av11 += g*xv1; av12 += g*xv2;
        float h = w11v * INV_SQRT2;
        av20 += h*(xv1*s3 - xv2*s2);
        av21 += h*(xv2*s1 - xv0*s3);
        av22 += h*(xv0*s2 - xv1*s1);
    }
    g_as[(size_t)n*64 + lane]      = as0 * INV_NEI;
    g_as[(size_t)n*64 + 32 + lane] = as1 * INV_NEI;
    float* avp = g_av + (size_t)n*288;
    avp[0*96 +      lane] = av00*INV_NEI; avp[0*96 + 32 + lane] = av10*INV_NEI; avp[0*96 + 64 + lane] = av20*INV_NEI;
    avp[1*96 +      lane] = av01*INV_NEI; avp[1*96 + 32 + lane] = av11*INV_NEI; avp[1*96 + 64 + lane] = av21*INV_NEI;
    avp[2*96 +      lane] = av02*INV_NEI; avp[2*96 + 32 + lane] = av12*INV_NEI; avp[2*96 + 64 + lane] = av22*INV_NEI;
}

// ---------------- final scalar: y_s, out_s, gates ----------------
__global__ __launch_bounds__(128) void k_final_s(const float* __restrict__ nf,
                                                 const float* __restrict__ attrs,
                                                 const float* __restrict__ W2s,
                                                 const float* __restrict__ Wscs,
                                                 float* __restrict__ out) {
    int n = blockIdx.x * 128 + threadIdx.x;
    if (n >= NN) return;
    float y[64];
    #pragma unroll
    for (int o = 0; o < 64; o++) y[o] = 0.f;
    const float* as = g_as + (size_t)n * 64;
    for (int k = 0; k < 64; k++) {
        float z = as[k];
        const float4* w = (const float4*)(W2s + k*64);
        #pragma unroll
        for (int j = 0; j < 16; j++) {
            float4 ww = __ldg(w + j);
            y[4*j] += z*ww.x; y[4*j+1] += z*ww.y; y[4*j+2] += z*ww.z; y[4*j+3] += z*ww.w;
        }
    }
    float at[16];
    {
        const float4* ap = (const float4*)(attrs + (size_t)n * 16);
        #pragma unroll
        for (int q = 0; q < 4; q++) {
            float4 a4 = ap[q];
            at[4*q]=a4.x; at[4*q+1]=a4.y; at[4*q+2]=a4.z; at[4*q+3]=a4.w;
        }
    }
    for (int u = 0; u < 32; u++) {
        float su = nf[(size_t)n*128 + u];
        for (int a = 0; a < 16; a++) {
            float z = su * at[a];
            const float4* w = (const float4*)(Wscs + (size_t)u*1024 + a*64);
            #pragma unroll
            for (int j = 0; j < 16; j++) {
                float4 ww = __ldg(w + j);
                y[4*j] += z*ww.x; y[4*j+1] += z*ww.y; y[4*j+2] += z*ww.z; y[4*j+3] += z*ww.w;
            }
        }
    }
    #pragma unroll
    for (int o = 0; o < 32; o++)
        out[(size_t)n*128 + o] = nf[(size_t)n*128 + o] + silu_f(y[o]);
    #pragma unroll
    for (int o = 0; o < 32; o++)
        g_gate[(size_t)n*32 + o] = silu_f(y[32 + o]);
}

// ---------------- final vector: one thread per (n, c) ----------------
__global__ __launch_bounds__(192) void k_final_v(const float* __restrict__ nf,
                                                 const float* __restrict__ attrs,
                                                 const float* __restrict__ W2v,
                                                 const float* __restrict__ Wscv,
                                                 float* __restrict__ out) {
    int gid = blockIdx.x * 192 + threadIdx.x;
    if (gid >= NN * 3) return;
    int n = gid / 3, c = gid - 3 * n;
    float y[32];
    #pragma unroll
    for (int o = 0; o < 32; o++) y[o] = 0.f;
    const float* av = g_av + (size_t)n*288 + c*96;
    for (int u = 0; u < 96; u++) {
        float z = av[u];
        const float4* w = (const float4*)(W2v + u*32);
        #pragma unroll
        for (int j = 0; j < 8; j++) {
            float4 ww = __ldg(w + j);
            y[4*j] += z*ww.x; y[4*j+1] += z*ww.y; y[4*j+2] += z*ww.z; y[4*j+3] += z*ww.w;
        }
    }
    float at[16];
    #pragma unroll
    for (int a = 0; a < 16; a++) at[a] = attrs[(size_t)n*16 + a];
    for (int u = 0; u < 32; u++) {
        float vu = nf[(size_t)n*128 + 32 + 3*u + c];
        for (int a = 0; a < 16; a++) {
            float z = vu * at[a];
            const float4* w = (const float4*)(Wscv + (size_t)u*512 + a*32);
            #pragma unroll
            for (int j = 0; j < 8; j++) {
                float4 ww = __ldg(w + j);
                y[4*j] += z*ww.x; y[4*j+1] += z*ww.y; y[4*j+2] += z*ww.z; y[4*j+3] += z*ww.w;
            }
        }
    }
    #pragma unroll
    for (int o = 0; o < 32; o++) {
        float g = g_gate[(size_t)n*32 + o];
        size_t oi = (size_t)n*128 + 32 + 3*o + c;
        out[oi] = nf[oi] + y[o] * g;
    }
}

extern "C" void kernel_launch(void* const* d_in, const int* in_sizes, int n_in,
                              void* d_out, int out_size) {
    const float* node_feats = (const float*)d_in[0];
    const float* node_attrs = (const float*)d_in[1];
    const float* edge_emb   = (const float*)d_in[2];
    const float* edge_attrs = (const float*)d_in[3];
    const int*   edge_src   = (const int*)d_in[4];
    const int*   edge_dst   = (const int*)d_in[5];
    const float* W1_s  = (const float*)d_in[6];
    const float* W1_v  = (const float*)d_in[7];
    const float* fc_w1 = (const float*)d_in[8];
    const float* fc_b1 = (const float*)d_in[9];
    const float* fc_w2 = (const float*)d_in[10];
    const float* W2_s  = (const float*)d_in[11];
    const float* W2_v  = (const float*)d_in[12];
    const float* Wsc_s = (const float*)d_in[13];
    const float* Wsc_v = (const float*)d_in[14];
    float* out = (float*)d_out;

    k_zero<<<(NN + 255) / 256, 256>>>();
    k_hist<<<(NE + 255) / 256, 256>>>(edge_dst);
    k_scan<<<1, 1024>>>();
    k_scatter<<<(NE + 255) / 256, 256>>>(edge_dst);
    k_stageA<<<(NN + 255) / 256, 256>>>(node_feats, W1_s, W1_v);
    k_mlp<<<(NE + 127) / 128, 128>>>(edge_emb, fc_w1, fc_b1, fc_w2);
    k_agg<<<(NN * 32 + 255) / 256, 256>>>(edge_src, edge_attrs);
    k_final_s<<<(NN + 127) / 128, 128>>>(node_feats, node_attrs, W2_s, Wsc_s, out);
    k_final_v<<<(NN * 3 + 191) / 192, 192>>>(node_feats, node_attrs, W2_v, Wsc_v, out);
}

// round 3
// speedup vs baseline: 1.9850x; 1.9850x over previous
#include <cuda_runtime.h>
#include <cstdint>

#define NN 50000
#define NE 800000
typedef unsigned long long ull;

static __device__ __forceinline__ ull ffma2(ull a, ull b, ull c) {
    ull d; asm("fma.rn.f32x2 %0, %1, %2, %3;" : "=l"(d) : "l"(a), "l"(b), "l"(c)); return d;
}
static __device__ __forceinline__ ull pack2(float lo, float hi) {
    ull d; asm("mov.b64 %0, {%1, %2};" : "=l"(d) : "f"(lo), "f"(hi)); return d;
}
static __device__ __forceinline__ float2 unpack2(ull v) {
    float2 r; asm("mov.b64 {%0, %1}, %2;" : "=f"(r.x), "=f"(r.y) : "l"(v)); return r;
}
static __device__ __forceinline__ float silu_f(float x) { return __fdividef(x, 1.0f + __expf(-x)); }

#define INV_SQRT3 0.5773502691896258f
#define INV_SQRT2 0.7071067811865476f
#define INV_NEI   0.25f

__device__ int   g_count[NN];
__device__ int   g_off[NN + 1];
__device__ int   g_cursor[NN];
__device__ int   g_perm[NE];
__device__ float g_xs[NN * 32];
__device__ float g_xv[NN * 96];          // [n][c][32]
__device__ float g_w[(size_t)NE * 160];  // [e][160]
__device__ float g_as[NN * 64];
__device__ float g_av[NN * 288];         // [n][c][96]
__device__ float g_gate[NN * 32];

// ---------------- sort by dst ----------------
__global__ void k_zero() {
    int i = blockIdx.x * blockDim.x + threadIdx.x;
    if (i < NN) g_count[i] = 0;
}
__global__ void k_hist(const int* __restrict__ edst) {
    int e = blockIdx.x * blockDim.x + threadIdx.x;
    if (e < NE) atomicAdd(&g_count[edst[e]], 1);
}
__global__ void k_scan() {
    __shared__ int wsum[32];
    int tid = threadIdx.x, lane = tid & 31, wid = tid >> 5;
    int running = 0;
    for (int base = 0; base < NN; base += 1024) {
        int i = base + tid;
        int c = (i < NN) ? g_count[i] : 0;
        int x = c;
        #pragma unroll
        for (int d = 1; d < 32; d <<= 1) {
            int y = __shfl_up_sync(0xffffffffu, x, d);
            if (lane >= d) x += y;
        }
        if (lane == 31) wsum[wid] = x;
        __syncthreads();
        if (wid == 0) {
            int s = wsum[lane];
            #pragma unroll
            for (int d = 1; d < 32; d <<= 1) {
                int y = __shfl_up_sync(0xffffffffu, s, d);
                if (lane >= d) s += y;
            }
            wsum[lane] = s;
        }
        __syncthreads();
        int prev = (wid > 0) ? wsum[wid - 1] : 0;
        int excl = running + prev + x - c;
        if (i < NN) { g_off[i] = excl; g_cursor[i] = excl; }
        running += wsum[31];
        __syncthreads();
    }
    if (tid == 0) g_off[NN] = running;
}
__global__ void k_scatter(const int* __restrict__ edst) {
    int e = blockIdx.x * blockDim.x + threadIdx.x;
    if (e < NE) g_perm[atomicAdd(&g_cursor[edst[e]], 1)] = e;
}

// ---------------- stage A: x_s = s@W1s, x_v = einsum(v,W1v) ----------------
__global__ __launch_bounds__(256) void k_stageA(const float* __restrict__ nf,
                                                const float* __restrict__ W1s,
                                                const float* __restrict__ W1v) {
    __shared__ float sw[2048];  // W1s 1024 + W1v 1024
    int tid = threadIdx.x;
    for (int i = tid; i < 1024; i += 256) { sw[i] = W1s[i]; sw[1024 + i] = W1v[i]; }
    __syncthreads();
    int n = blockIdx.x * blockDim.x + tid;
    if (n >= NN) return;
    float s[32];
    const float4* p = (const float4*)(nf + (size_t)n * 128);
    #pragma unroll
    for (int q = 0; q < 8; q++) {
        float4 f = p[q];
        s[4*q] = f.x; s[4*q+1] = f.y; s[4*q+2] = f.z; s[4*q+3] = f.w;
    }
    #pragma unroll 2
    for (int og = 0; og < 8; og++) {
        float4 acc = make_float4(0.f,0.f,0.f,0.f);
        #pragma unroll
        for (int u = 0; u < 32; u++) {
            float4 w = *(const float4*)(sw + u*32 + og*4);
            acc.x += s[u]*w.x; acc.y += s[u]*w.y; acc.z += s[u]*w.z; acc.w += s[u]*w.w;
        }
        *(float4*)(g_xs + (size_t)n*32 + og*4) = acc;
    }
    for (int c = 0; c < 3; c++) {
        float vc[32];
        #pragma unroll
        for (int u = 0; u < 32; u++) vc[u] = nf[(size_t)n*128 + 32 + 3*u + c];
        #pragma unroll 2
        for (int og = 0; og < 8; og++) {
            float4 acc = make_float4(0.f,0.f,0.f,0.f);
            #pragma unroll
            for (int u = 0; u < 32; u++) {
                float4 w = *(const float4*)(sw + 1024 + u*32 + og*4);
                acc.x += vc[u]*w.x; acc.y += vc[u]*w.y; acc.z += vc[u]*w.z; acc.w += vc[u]*w.w;
            }
            *(float4*)(g_xv + (size_t)n*96 + c*32 + og*4) = acc;
        }
    }
}

// ---------------- edge MLP: w = silu(emb@fc1+b)@fc2 ----------------
// Weights staged in shared; hidden layer kept in registers; f32x2 FMA.
__global__ __launch_bounds__(256) void k_mlp(const float* __restrict__ emb,
                                             const float* __restrict__ w1,
                                             const float* __restrict__ b1,
                                             const float* __restrict__ w2) {
    __shared__ float sbuf[10240];  // 40KB: phase1 w1(512)+b1(64), phase2 w2(10240)
    int tid = threadIdx.x;
    // phase 1 weights
    for (int i = tid; i < 512; i += 256) sbuf[i] = w1[i];
    if (tid < 64) sbuf[512 + tid] = b1[tid];
    __syncthreads();

    int e = blockIdx.x * 256 + tid;
    bool ok = (e < NE);
    int ee = ok ? e : 0;
    float x[8];
    {
        const float4* ep = (const float4*)(emb + (size_t)ee * 8);
        float4 xa = ep[0], xb = ep[1];
        x[0]=xa.x; x[1]=xa.y; x[2]=xa.z; x[3]=xa.w;
        x[4]=xb.x; x[5]=xb.y; x[6]=xb.z; x[7]=xb.w;
    }
    float h[64];
    #pragma unroll
    for (int j = 0; j < 64; j += 4) {
        float4 b = *(const float4*)(sbuf + 512 + j);
        h[j]=b.x; h[j+1]=b.y; h[j+2]=b.z; h[j+3]=b.w;
    }
    #pragma unroll
    for (int i = 0; i < 8; i++) {
        float xi = x[i];
        #pragma unroll
        for (int j = 0; j < 64; j += 4) {
            float4 w = *(const float4*)(sbuf + i*64 + j);
            h[j] += xi*w.x; h[j+1] += xi*w.y; h[j+2] += xi*w.z; h[j+3] += xi*w.w;
        }
    }
    #pragma unroll
    for (int j = 0; j < 64; j++) h[j] = silu_f(h[j]);

    __syncthreads();
    // phase 2 weights
    for (int i = tid; i < 10240; i += 256) sbuf[i] = w2[i];
    __syncthreads();
    if (!ok) return;

    for (int ob = 0; ob < 20; ob++) {
        ull a0=0ULL, a1=0ULL, a2=0ULL, a3=0ULL;
        const float* wb = sbuf + ob*8;
        #pragma unroll
        for (int k = 0; k < 64; k++) {
            ull h2 = pack2(h[k], h[k]);
            const ulonglong2* wp = (const ulonglong2*)(wb + k*160);
            ulonglong2 wA = wp[0];
            a0 = ffma2(h2, wA.x, a0);
            a1 = ffma2(h2, wA.y, a1);
            ulonglong2 wB = wp[1];
            a2 = ffma2(h2, wB.x, a2);
            a3 = ffma2(h2, wB.y, a3);
        }
        float2 r0 = unpack2(a0), r1 = unpack2(a1), r2 = unpack2(a2), r3 = unpack2(a3);
        float4* op = (float4*)(g_w + (size_t)e*160 + ob*8);
        op[0] = make_float4(r0.x, r0.y, r1.x, r1.y);
        op[1] = make_float4(r2.x, r2.y, r3.x, r3.y);
    }
}

// ---------------- aggregation: warp per node ----------------
__global__ __launch_bounds__(256) void k_agg(const int* __restrict__ esrc,
                                             const float* __restrict__ eattr) {
    int n = (blockIdx.x * 256 + threadIdx.x) >> 5;
    int lane = threadIdx.x & 31;
    if (n >= NN) return;
    int start = g_off[n], end = g_off[n + 1];
    float as0=0, as1=0;
    float av00=0, av01=0, av02=0, av10=0, av11=0, av12=0, av20=0, av21=0, av22=0;
    for (int idx = start; idx < end; idx++) {
        int e = __ldg(g_perm + idx);
        int src = __ldg(esrc + e);
        float4 ea = __ldg((const float4*)(eattr + (size_t)e * 4));
        float sh0 = ea.x, s1 = ea.y, s2 = ea.z, s3 = ea.w;
        float xs  = g_xs[(size_t)src*32 + lane];
        const float* xvp = g_xv + (size_t)src*96;
        float xv0 = xvp[lane], xv1 = xvp[32+lane], xv2 = xvp[64+lane];
        const float* we = g_w + (size_t)e*160;
        float w00 = we[lane], w01 = we[32+lane], w10 = we[64+lane];
        float w11s = we[96+lane], w11v = we[128+lane];

        as0 += w00 * xs * sh0;
        as1 += (w11s * INV_SQRT3) * (xv0*s1 + xv1*s2 + xv2*s3);
        float t = w01 * xs;
        av00 += t*s1; av01 += t*s2; av02 += t*s3;
        float g = w10 * sh0;
        av10 += g*xv0; av11 += g*xv1; av12 += g*xv2;
        float h = w11v * INV_SQRT2;
        av20 += h*(xv1*s3 - xv2*s2);
        av21 += h*(xv2*s1 - xv0*s3);
        av22 += h*(xv0*s2 - xv1*s1);
    }
    g_as[(size_t)n*64 + lane]      = as0 * INV_NEI;
    g_as[(size_t)n*64 + 32 + lane] = as1 * INV_NEI;
    float* avp = g_av + (size_t)n*288;
    avp[0*96 +      lane] = av00*INV_NEI; avp[0*96 + 32 + lane] = av10*INV_NEI; avp[0*96 + 64 + lane] = av20*INV_NEI;
    avp[1*96 +      lane] = av01*INV_NEI; avp[1*96 + 32 + lane] = av11*INV_NEI; avp[1*96 + 64 + lane] = av21*INV_NEI;
    avp[2*96 +      lane] = av02*INV_NEI; avp[2*96 + 32 + lane] = av12*INV_NEI; avp[2*96 + 64 + lane] = av22*INV_NEI;
}

// ---------------- final scalar: y_s, out_s, gates ----------------
// Weights staged in 16KB shared (reused buffer), f32x2 accumulation.
__global__ __launch_bounds__(256) void k_final_s(const float* __restrict__ nf,
                                                 const float* __restrict__ attrs,
                                                 const float* __restrict__ W2s,
                                                 const float* __restrict__ Wscs,
                                                 float* __restrict__ out) {
    __shared__ float sbuf[4096];  // 16KB
    int tid = threadIdx.x;
    int n = blockIdx.x * 256 + tid;
    bool ok = (n < NN);
    int nn = ok ? n : 0;

    ull y[32];
    #pragma unroll
    for (int j = 0; j < 32; j++) y[j] = 0ULL;

    // phase 1: y += a_s @ W2_s
    for (int i = tid; i < 4096; i += 256) sbuf[i] = W2s[i];
    __syncthreads();
    {
        const float* as = g_as + (size_t)nn * 64;
        for (int k = 0; k < 64; k++) {
            float z = ok ? as[k] : 0.f;
            ull zz = pack2(z, z);
            const ulonglong2* w = (const ulonglong2*)(sbuf + k*64);
            #pragma unroll
            for (int j = 0; j < 16; j++) {
                ulonglong2 wp = w[j];
                y[2*j]   = ffma2(zz, wp.x, y[2*j]);
                y[2*j+1] = ffma2(zz, wp.y, y[2*j+1]);
            }
        }
    }
    float at[16];
    {
        const float4* ap = (const float4*)(attrs + (size_t)nn * 16);
        #pragma unroll
        for (int q = 0; q < 4; q++) {
            float4 a4 = ap[q];
            at[4*q]=a4.x; at[4*q+1]=a4.y; at[4*q+2]=a4.z; at[4*q+3]=a4.w;
        }
    }
    // phase 2: self-connection, chunks of 4 u (4096 floats each)
    for (int ch = 0; ch < 8; ch++) {
        __syncthreads();
        for (int i = tid; i < 4096; i += 256) sbuf[i] = Wscs[ch*4096 + i];
        __syncthreads();
        #pragma unroll
        for (int uu = 0; uu < 4; uu++) {
            float su = ok ? nf[(size_t)nn*128 + ch*4 + uu] : 0.f;
            for (int a = 0; a < 16; a++) {
                float z = su * at[a];
                ull zz = pack2(z, z);
                const ulonglong2* w = (const ulonglong2*)(sbuf + uu*1024 + a*64);
                #pragma unroll
                for (int j = 0; j < 16; j++) {
                    ulonglong2 wp = w[j];
                    y[2*j]   = ffma2(zz, wp.x, y[2*j]);
                    y[2*j+1] = ffma2(zz, wp.y, y[2*j+1]);
                }
            }
        }
    }
    if (!ok) return;
    #pragma unroll
    for (int j = 0; j < 16; j++) {
        float2 v = unpack2(y[j]);
        out[(size_t)n*128 + 2*j]     = nf[(size_t)n*128 + 2*j]     + silu_f(v.x);
        out[(size_t)n*128 + 2*j + 1] = nf[(size_t)n*128 + 2*j + 1] + silu_f(v.y);
    }
    #pragma unroll
    for (int j = 16; j < 32; j++) {
        float2 v = unpack2(y[j]);
        g_gate[(size_t)n*32 + 2*j - 32] = silu_f(v.x);
        g_gate[(size_t)n*32 + 2*j - 31] = silu_f(v.y);
    }
}

// ---------------- final vector: grid.y = component c ----------------
__global__ __launch_bounds__(256) void k_final_v(const float* __restrict__ nf,
                                                 const float* __restrict__ attrs,
                                                 const float* __restrict__ W2v,
                                                 const float* __restrict__ Wscv,
                                                 float* __restrict__ out) {
    __shared__ float sbuf[4096];  // 16KB
    int tid = threadIdx.x;
    int c = blockIdx.y;
    int n = blockIdx.x * 256 + tid;
    bool ok = (n < NN);
    int nn = ok ? n : 0;

    ull y[16];
    #pragma unroll
    for (int j = 0; j < 16; j++) y[j] = 0ULL;

    // phase 1: y += a_v[:,c] @ W2_v  (96x32)
    for (int i = tid; i < 3072; i += 256) sbuf[i] = W2v[i];
    __syncthreads();
    {
        const float* av = g_av + (size_t)nn*288 + c*96;
        for (int u = 0; u < 96; u++) {
            float z = ok ? av[u] : 0.f;
            ull zz = pack2(z, z);
            const ulonglong2* w = (const ulonglong2*)(sbuf + u*32);
            #pragma unroll
            for (int j = 0; j < 8; j++) {
                ulonglong2 wp = w[j];
                y[2*j]   = ffma2(zz, wp.x, y[2*j]);
                y[2*j+1] = ffma2(zz, wp.y, y[2*j+1]);
            }
        }
    }
    float at[16];
    {
        const float4* ap = (const float4*)(attrs + (size_t)nn * 16);
        #pragma unroll
        for (int q = 0; q < 4; q++) {
            float4 a4 = ap[q];
            at[4*q]=a4.x; at[4*q+1]=a4.y; at[4*q+2]=a4.z; at[4*q+3]=a4.w;
        }
    }
    // phase 2: self-connection, chunks of 8 u (4096 floats each)
    for (int ch = 0; ch < 4; ch++) {
        __syncthreads();
        for (int i = tid; i < 4096; i += 256) sbuf[i] = Wscv[ch*4096 + i];
        __syncthreads();
        #pragma unroll
        for (int uu = 0; uu < 8; uu++) {
            int u = ch*8 + uu;
            float vu = ok ? nf[(size_t)nn*128 + 32 + 3*u + c] : 0.f;
            for (int a = 0; a < 16; a++) {
                float z = vu * at[a];
                ull zz = pack2(z, z);
                const ulonglong2* w = (const ulonglong2*)(sbuf + uu*512 + a*32);
                #pragma unroll
                for (int j = 0; j < 8; j++) {
                    ulonglong2 wp = w[j];
                    y[2*j]   = ffma2(zz, wp.x, y[2*j]);
                    y[2*j+1] = ffma2(zz, wp.y, y[2*j+1]);
                }
            }
        }
    }
    if (!ok) return;
    #pragma unroll
    for (int j = 0; j < 16; j++) {
        float2 v = unpack2(y[j]);
        int o0 = 2*j, o1 = 2*j + 1;
        float g0 = g_gate[(size_t)n*32 + o0];
        float g1 = g_gate[(size_t)n*32 + o1];
        size_t i0 = (size_t)n*128 + 32 + 3*o0 + c;
        size_t i1 = (size_t)n*128 + 32 + 3*o1 + c;
        out[i0] = nf[i0] + v.x * g0;
        out[i1] = nf[i1] + v.y * g1;
    }
}

extern "C" void kernel_launch(void* const* d_in, const int* in_sizes, int n_in,
                              void* d_out, int out_size) {
    const float* node_feats = (const float*)d_in[0];
    const float* node_attrs = (const float*)d_in[1];
    const float* edge_emb   = (const float*)d_in[2];
    const float* edge_attrs = (const float*)d_in[3];
    const int*   edge_src   = (const int*)d_in[4];
    const int*   edge_dst   = (const int*)d_in[5];
    const float* W1_s  = (const float*)d_in[6];
    const float* W1_v  = (const float*)d_in[7];
    const float* fc_w1 = (const float*)d_in[8];
    const float* fc_b1 = (const float*)d_in[9];
    const float* fc_w2 = (const float*)d_in[10];
    const float* W2_s  = (const float*)d_in[11];
    const float* W2_v  = (const float*)d_in[12];
    const float* Wsc_s = (const float*)d_in[13];
    const float* Wsc_v = (const float*)d_in[14];
    float* out = (float*)d_out;

    k_zero<<<(NN + 255) / 256, 256>>>();
    k_hist<<<(NE + 255) / 256, 256>>>(edge_dst);
    k_scan<<<1, 1024>>>();
    k_scatter<<<(NE + 255) / 256, 256>>>(edge_dst);
    k_stageA<<<(NN + 255) / 256, 256>>>(node_feats, W1_s, W1_v);
    k_mlp<<<(NE + 255) / 256, 256>>>(edge_emb, fc_w1, fc_b1, fc_w2);
    k_agg<<<(NN * 32 + 255) / 256, 256>>>(edge_src, edge_attrs);
    k_final_s<<<(NN + 255) / 256, 256>>>(node_feats, node_attrs, W2_s, Wsc_s, out);
    dim3 gv((NN + 255) / 256, 3);
    k_final_v<<<gv, 256>>>(node_feats, node_attrs, W2_v, Wsc_v, out);
}